// round 2
// baseline (speedup 1.0000x reference)
#include <cuda_runtime.h>
#include <cstdint>

// Problem constants (fixed by setup_inputs)
#define BB 4
#define NN 16384
#define MM 128
#define CC 128
#define SS 512
#define ROW 131            // 3 + C floats per sample
#define NBOX (BB*MM)       // 512
#define POOLED_ELEMS ((size_t)NBOX * SS * ROW)   // 34,340,864

// Scratch (device globals — no allocation allowed)
__device__ int g_idx[NBOX * SS];   // first min(cnt,512) inside indices per box
__device__ int g_cnt[NBOX];        // collected count (>=512 means "at least 512")

// ---------------------------------------------------------------------------
// Phase 1: per-box stable inside-point index collection with early exit.
// One block (256 threads) per (b, m) box.
// ---------------------------------------------------------------------------
__global__ __launch_bounds__(256)
void phase1_kernel(const float* __restrict__ points,
                   const float* __restrict__ boxes) {
    const int bm = blockIdx.x;          // 0..511
    const int b  = bm >> 7;             // /M (M=128)

    // Box params
    const float* box = boxes + bm * 7;
    const float cx = box[0];
    const float cy = box[1];
    float cz       = box[2];
    const float dx = box[3];
    const float dy = box[4];
    const float dz = box[5];
    const float rz = box[6];
    cz = __fadd_rn(cz, __fmul_rn(dz, 0.5f));        // bottom-center -> center
    const float cosa = cosf(-rz);
    const float sina = sinf(-rz);
    const float hx = __fmul_rn(dx, 0.5f);
    const float hy = __fmul_rn(dy, 0.5f);
    const float hz = __fmul_rn(dz, 0.5f);

    const float* pts = points + (size_t)b * NN * 3;

    __shared__ int warp_cnt[8];

    const int tid  = threadIdx.x;
    const int lane = tid & 31;
    const int wid  = tid >> 5;

    int collected = 0;

    for (int base = 0; base < NN; base += 256) {
        const int i = base + tid;       // NN % 256 == 0, no bounds check
        const float px = pts[i * 3 + 0];
        const float py = pts[i * 3 + 1];
        const float pz = pts[i * 3 + 2];

        const float sx = __fsub_rn(px, cx);
        const float sy = __fsub_rn(py, cy);
        const float sz = __fsub_rn(pz, cz);
        // no-FMA-contraction rotate to match XLA mul-then-add ordering
        const float lx = __fsub_rn(__fmul_rn(sx, cosa), __fmul_rn(sy, sina));
        const float ly = __fadd_rn(__fmul_rn(sx, sina), __fmul_rn(sy, cosa));

        const bool inside = (fabsf(lx) < hx) && (fabsf(ly) < hy) && (fabsf(sz) <= hz);

        const unsigned ball = __ballot_sync(0xffffffffu, inside);
        const int wsum = __popc(ball);
        const int wpos = __popc(ball & ((1u << lane) - 1u));
        if (lane == 0) warp_cnt[wid] = wsum;
        __syncthreads();

        int wbase = 0;
        #pragma unroll
        for (int w = 0; w < 8; w++) {
            const int c = warp_cnt[w];
            if (w < wid) wbase += c;
        }
        int total = 0;
        #pragma unroll
        for (int w = 0; w < 8; w++) total += warp_cnt[w];

        if (inside) {
            const int p = collected + wbase + wpos;
            if (p < SS) g_idx[bm * SS + p] = i;
        }
        collected += total;
        __syncthreads();   // warp_cnt reused next iteration

        // Once >= S indices collected, k % cnt == k for all k < S: stop scanning.
        if (collected >= SS) break;
    }

    if (tid == 0) g_cnt[bm] = collected;
}

// ---------------------------------------------------------------------------
// Phase 2: gather. One warp per output sample row (131 floats).
// ---------------------------------------------------------------------------
__global__ __launch_bounds__(256)
void phase2_kernel(const float* __restrict__ points,
                   const float* __restrict__ feats,
                   float* __restrict__ out) {
    const int gwarp = (int)((blockIdx.x * blockDim.x + threadIdx.x) >> 5);
    const int lane  = threadIdx.x & 31;
    // gwarp in [0, NBOX*SS)
    const int s  = gwarp & (SS - 1);
    const int bm = gwarp >> 9;          // /S
    const int b  = bm >> 7;             // /M

    float* o = out + (size_t)gwarp * ROW;

    const int cnt = g_cnt[bm];
    if (cnt == 0) {
        #pragma unroll
        for (int j = lane; j < ROW; j += 32) o[j] = 0.0f;
        return;
    }

    // cnt may be a truncated count (>=512) — then s % cnt == s since s < 512.
    const int r   = s % cnt;
    const int idx = g_idx[bm * SS + r];

    const float*  p = points + ((size_t)b * NN + idx) * 3;
    const float4* f = (const float4*)(feats + ((size_t)b * NN + idx) * CC);

    if (lane < 3) o[lane] = p[lane];

    const float4 v = f[lane];           // 32 lanes x float4 = full 128-float row
    float* od = o + 3 + lane * 4;
    od[0] = v.x; od[1] = v.y; od[2] = v.z; od[3] = v.w;
}

// ---------------------------------------------------------------------------
// empty_flag tail (written as 0.0f / 1.0f into the float output buffer)
// ---------------------------------------------------------------------------
__global__ void flags_kernel(float* __restrict__ out) {
    const int i = blockIdx.x * blockDim.x + threadIdx.x;
    if (i < NBOX) out[POOLED_ELEMS + i] = (g_cnt[i] > 0) ? 0.0f : 1.0f;
}

extern "C" void kernel_launch(void* const* d_in, const int* in_sizes, int n_in,
                              void* d_out, int out_size) {
    const float* points = (const float*)d_in[0];   // (B, N, 3)
    const float* feats  = (const float*)d_in[1];   // (B, N, C)
    const float* boxes  = (const float*)d_in[2];   // (B, M, 7)
    float* out = (float*)d_out;

    phase1_kernel<<<NBOX, 256>>>(points, boxes);

    // One warp per sample row: NBOX*SS warps = 262144 warps -> 32768 blocks of 256
    const int total_warps = NBOX * SS;
    phase2_kernel<<<total_warps / 8, 256>>>(points, feats, out);

    if ((size_t)out_size >= POOLED_ELEMS + NBOX) {
        flags_kernel<<<(NBOX + 255) / 256, 256>>>(out);
    }
}

// round 3
// speedup vs baseline: 1.5650x; 1.5650x over previous
#include <cuda_runtime.h>
#include <cstdint>

// Problem constants (fixed by setup_inputs)
#define BB 4
#define NN 16384
#define MM 128
#define CC 128
#define SS 512
#define ROW 131            // 3 + C floats per sample
#define NBOX (BB*MM)       // 512
#define WPB  (NN/32)       // 512 mask words per box
#define POOLED_ELEMS ((size_t)NBOX * SS * ROW)   // 34,340,864

// Scratch (device globals — no allocation allowed)
__device__ unsigned g_mask[NBOX * WPB];  // [bm][word] inside-bitmask, 1MB
__device__ int g_idx[NBOX * SS];         // first min(cnt,512) inside indices per box
__device__ int g_cnt[NBOX];              // exact inside count

// ---------------------------------------------------------------------------
// Stage 1: mask kernel. Each thread owns one point (registers), loops over the
// 128 boxes of its batch (params staged in shared as 2x float4). lane0 of each
// warp stores the 32-bit ballot per box.
// Grid: 256 blocks x 256 threads. Block covers 256 consecutive points.
// ---------------------------------------------------------------------------
__global__ __launch_bounds__(256)
void mask_kernel(const float* __restrict__ points,
                 const float* __restrict__ boxes) {
    const int blk   = blockIdx.x;        // 0..255
    const int b     = blk >> 6;          // batch  (64 blocks per batch)
    const int pbase = (blk & 63) * 256;  // first point in batch for this block

    // Box params: p0 = (cx, cy, cz_center, hz), p1 = (cosa, sina, hx, hy)
    __shared__ float4 sb0[MM];
    __shared__ float4 sb1[MM];

    const int tid = threadIdx.x;
    if (tid < MM) {
        const float* box = boxes + (b * MM + tid) * 7;
        const float cx = box[0];
        const float cy = box[1];
        const float cz = __fadd_rn(box[2], __fmul_rn(box[5], 0.5f));
        const float dx = box[3];
        const float dy = box[4];
        const float dz = box[5];
        const float rz = box[6];
        sb0[tid] = make_float4(cx, cy, cz, __fmul_rn(dz, 0.5f));
        sb1[tid] = make_float4(cosf(-rz), sinf(-rz),
                               __fmul_rn(dx, 0.5f), __fmul_rn(dy, 0.5f));
    }

    const int pi   = pbase + tid;                 // point index within batch
    const float* p = points + ((size_t)b * NN + pi) * 3;
    const float px = p[0];
    const float py = p[1];
    const float pz = p[2];

    __syncthreads();

    const int lane = tid & 31;
    const int word = pi >> 5;                     // mask word within batch
    unsigned* mrow = g_mask + (size_t)b * MM * WPB + word;

    #pragma unroll 4
    for (int m = 0; m < MM; m++) {
        const float4 q0 = sb0[m];
        const float4 q1 = sb1[m];
        const float sx = __fsub_rn(px, q0.x);
        const float sy = __fsub_rn(py, q0.y);
        const float sz = __fsub_rn(pz, q0.z);
        // no-FMA-contraction rotate to match XLA mul-then-add ordering
        const float lx = __fsub_rn(__fmul_rn(sx, q1.x), __fmul_rn(sy, q1.y));
        const float ly = __fadd_rn(__fmul_rn(sx, q1.y), __fmul_rn(sy, q1.x));
        const bool inside = (fabsf(lx) < q1.z) && (fabsf(ly) < q1.w)
                          && (fabsf(sz) <= q0.w);
        const unsigned ball = __ballot_sync(0xffffffffu, inside);
        if (lane == 0) mrow[(size_t)m * WPB] = ball;
    }
}

// ---------------------------------------------------------------------------
// Stage 2: compaction. One 512-thread block per box. Block prefix scan over
// per-word popcounts, then expand set bits (stable order) into g_idx[0..511].
// Also writes exact cnt and the empty flag.
// ---------------------------------------------------------------------------
__global__ __launch_bounds__(512)
void compact_kernel(float* __restrict__ flags) {
    const int bm  = blockIdx.x;
    const int t   = threadIdx.x;         // 0..511 (one mask word each)
    const int lane = t & 31;
    const int wid  = t >> 5;             // 0..15

    const unsigned w = g_mask[(size_t)bm * WPB + t];
    const int c = __popc(w);

    // warp inclusive scan of counts
    int incl = c;
    #pragma unroll
    for (int d = 1; d < 32; d <<= 1) {
        int v = __shfl_up_sync(0xffffffffu, incl, d);
        if (lane >= d) incl += v;
    }

    __shared__ int wsum[16];
    __shared__ int stotal;
    if (lane == 31) wsum[wid] = incl;
    __syncthreads();
    if (t < 16) {
        int v = wsum[t];
        #pragma unroll
        for (int d = 1; d < 16; d <<= 1) {
            int u = __shfl_up_sync(0xffffu, v, d);
            if (t >= d) v += u;
        }
        wsum[t] = v;
        if (t == 15) stotal = v;
    }
    __syncthreads();

    const int warp_excl = (wid == 0) ? 0 : wsum[wid - 1];
    int rank = warp_excl + incl - c;     // exclusive prefix = first output slot

    // expand set bits in order until rank hits 512
    unsigned ww = w;
    const int pbase = t * 32;
    while (ww && rank < SS) {
        const int bit = __ffs(ww) - 1;
        ww &= ww - 1;
        g_idx[bm * SS + rank] = pbase + bit;
        rank++;
    }

    if (t == 0) {
        const int total = stotal;
        g_cnt[bm] = total;
        if (flags) flags[bm] = (total > 0) ? 0.0f : 1.0f;
    }
}

// ---------------------------------------------------------------------------
// Stage 3: gather. One warp per output sample row (131 floats).
// ---------------------------------------------------------------------------
__global__ __launch_bounds__(256)
void phase2_kernel(const float* __restrict__ points,
                   const float* __restrict__ feats,
                   float* __restrict__ out) {
    const int gwarp = (int)((blockIdx.x * blockDim.x + threadIdx.x) >> 5);
    const int lane  = threadIdx.x & 31;
    const int s  = gwarp & (SS - 1);
    const int bm = gwarp >> 9;          // /S
    const int b  = bm >> 7;             // /M

    float* o = out + (size_t)gwarp * ROW;

    const int cnt = g_cnt[bm];
    if (cnt == 0) {
        #pragma unroll
        for (int j = lane; j < ROW; j += 32) o[j] = 0.0f;
        return;
    }

    const int r   = (s < cnt) ? s : (s % cnt);
    const int idx = g_idx[bm * SS + r];

    const float*  p = points + ((size_t)b * NN + idx) * 3;
    const float4* f = (const float4*)(feats + ((size_t)b * NN + idx) * CC);

    if (lane < 3) o[lane] = p[lane];

    const float4 v = f[lane];           // 32 lanes x float4 = full 128-float row
    float* od = o + 3 + lane * 4;
    od[0] = v.x; od[1] = v.y; od[2] = v.z; od[3] = v.w;
}

extern "C" void kernel_launch(void* const* d_in, const int* in_sizes, int n_in,
                              void* d_out, int out_size) {
    const float* points = (const float*)d_in[0];   // (B, N, 3)
    const float* feats  = (const float*)d_in[1];   // (B, N, C)
    const float* boxes  = (const float*)d_in[2];   // (B, M, 7)
    float* out = (float*)d_out;

    float* flags = ((size_t)out_size >= POOLED_ELEMS + NBOX)
                 ? (out + POOLED_ELEMS) : nullptr;

    mask_kernel<<<256, 256>>>(points, boxes);
    compact_kernel<<<NBOX, 512>>>(flags);

    const int total_warps = NBOX * SS;             // one warp per sample row
    phase2_kernel<<<total_warps / 8, 256>>>(points, feats, out);
}

// round 4
// speedup vs baseline: 1.6788x; 1.0727x over previous
#include <cuda_runtime.h>
#include <cstdint>

// Problem constants (fixed by setup_inputs)
#define BB 4
#define NN 16384
#define MM 128
#define CC 128
#define SS 512
#define ROW 131            // 3 + C floats per sample
#define NBOX (BB*MM)       // 512
#define WPB  (NN/32)       // 512 mask words per box
#define BOXG 32            // boxes per mask-block (128/4 groups)
#define POOLED_ELEMS ((size_t)NBOX * SS * ROW)   // 34,340,864

// Scratch (device globals — no allocation allowed)
__device__ unsigned g_mask[NBOX * WPB];  // [bm][word] inside-bitmask, 1MB
__device__ int g_idx[NBOX * SS];         // first min(cnt,512) inside indices per box
__device__ int g_cnt[NBOX];              // exact inside count

// ---------------------------------------------------------------------------
// Stage 1: mask kernel. Each thread owns one point (registers), loops over a
// group of 32 boxes of its batch (params staged in shared). lane0 of each
// warp stores the 32-bit ballot per box.
// Grid: 1024 blocks x 256 threads (4 box-groups x 64 point-blocks x 4 batches).
// ---------------------------------------------------------------------------
__global__ __launch_bounds__(256)
void mask_kernel(const float* __restrict__ points,
                 const float* __restrict__ boxes) {
    const int blk   = blockIdx.x;        // 0..1023
    const int grp   = blk & 3;           // box group (32 boxes)
    const int pblk  = blk >> 2;          // 0..255
    const int b     = pblk >> 6;         // batch  (64 point-blocks per batch)
    const int pbase = (pblk & 63) * 256; // first point in batch for this block
    const int mbase = grp * BOXG;        // first box in group

    // Box params: p0 = (cx, cy, cz_center, hz), p1 = (cosa, sina, hx, hy)
    __shared__ float4 sb0[BOXG];
    __shared__ float4 sb1[BOXG];

    const int tid = threadIdx.x;
    if (tid < BOXG) {
        const float* box = boxes + (b * MM + mbase + tid) * 7;
        const float cx = box[0];
        const float cy = box[1];
        const float cz = __fadd_rn(box[2], __fmul_rn(box[5], 0.5f));
        const float dx = box[3];
        const float dy = box[4];
        const float dz = box[5];
        const float rz = box[6];
        sb0[tid] = make_float4(cx, cy, cz, __fmul_rn(dz, 0.5f));
        sb1[tid] = make_float4(cosf(-rz), sinf(-rz),
                               __fmul_rn(dx, 0.5f), __fmul_rn(dy, 0.5f));
    }

    const int pi   = pbase + tid;                 // point index within batch
    const float* p = points + ((size_t)b * NN + pi) * 3;
    const float px = p[0];
    const float py = p[1];
    const float pz = p[2];

    __syncthreads();

    const int lane = tid & 31;
    const int word = pi >> 5;                     // mask word within batch
    unsigned* mrow = g_mask + (size_t)(b * MM + mbase) * WPB + word;

    #pragma unroll 4
    for (int m = 0; m < BOXG; m++) {
        const float4 q0 = sb0[m];
        const float4 q1 = sb1[m];
        const float sx = __fsub_rn(px, q0.x);
        const float sy = __fsub_rn(py, q0.y);
        const float sz = __fsub_rn(pz, q0.z);
        // no-FMA-contraction rotate to match XLA mul-then-add ordering
        const float lx = __fsub_rn(__fmul_rn(sx, q1.x), __fmul_rn(sy, q1.y));
        const float ly = __fadd_rn(__fmul_rn(sx, q1.y), __fmul_rn(sy, q1.x));
        const bool inside = (fabsf(lx) < q1.z) && (fabsf(ly) < q1.w)
                          && (fabsf(sz) <= q0.w);
        const unsigned ball = __ballot_sync(0xffffffffu, inside);
        if (lane == 0) mrow[(size_t)m * WPB] = ball;
    }
}

// ---------------------------------------------------------------------------
// Stage 2: compaction. One 512-thread block per box. Block prefix scan over
// per-word popcounts, then expand set bits (stable order) into g_idx[0..511].
// Also writes exact cnt and the empty flag.
// ---------------------------------------------------------------------------
__global__ __launch_bounds__(512)
void compact_kernel(float* __restrict__ flags) {
    const int bm  = blockIdx.x;
    const int t   = threadIdx.x;         // 0..511 (one mask word each)
    const int lane = t & 31;
    const int wid  = t >> 5;             // 0..15

    const unsigned w = g_mask[(size_t)bm * WPB + t];
    const int c = __popc(w);

    // warp inclusive scan of counts
    int incl = c;
    #pragma unroll
    for (int d = 1; d < 32; d <<= 1) {
        int v = __shfl_up_sync(0xffffffffu, incl, d);
        if (lane >= d) incl += v;
    }

    __shared__ int wsum[16];
    __shared__ int stotal;
    if (lane == 31) wsum[wid] = incl;
    __syncthreads();
    if (t < 16) {
        int v = wsum[t];
        #pragma unroll
        for (int d = 1; d < 16; d <<= 1) {
            int u = __shfl_up_sync(0xffffu, v, d);
            if (t >= d) v += u;
        }
        wsum[t] = v;
        if (t == 15) stotal = v;
    }
    __syncthreads();

    const int warp_excl = (wid == 0) ? 0 : wsum[wid - 1];
    int rank = warp_excl + incl - c;     // exclusive prefix = first output slot

    // expand set bits in order until rank hits 512
    unsigned ww = w;
    const int pbase = t * 32;
    while (ww && rank < SS) {
        const int bit = __ffs(ww) - 1;
        ww &= ww - 1;
        g_idx[bm * SS + rank] = pbase + bit;
        rank++;
    }

    if (t == 0) {
        const int total = stotal;
        g_cnt[bm] = total;
        if (flags) flags[bm] = (total > 0) ? 0.0f : 1.0f;
    }
}

// ---------------------------------------------------------------------------
// Stage 3: gather. One warp per output sample row (131 floats).
// Streaming (.cs) stores keep the 32MB feature set resident in L2.
// ---------------------------------------------------------------------------
__global__ __launch_bounds__(256)
void phase2_kernel(const float* __restrict__ points,
                   const float* __restrict__ feats,
                   float* __restrict__ out) {
    const int gwarp = (int)((blockIdx.x * blockDim.x + threadIdx.x) >> 5);
    const int lane  = threadIdx.x & 31;
    const int s  = gwarp & (SS - 1);
    const int bm = gwarp >> 9;          // /S
    const int b  = bm >> 7;             // /M

    float* o = out + (size_t)gwarp * ROW;

    const int cnt = g_cnt[bm];
    if (cnt == 0) {
        #pragma unroll
        for (int j = lane; j < ROW; j += 32) __stcs(o + j, 0.0f);
        return;
    }

    const int r   = (s < cnt) ? s : (s % cnt);
    const int idx = g_idx[bm * SS + r];

    const float*  p = points + ((size_t)b * NN + idx) * 3;
    const float4* f = (const float4*)(feats + ((size_t)b * NN + idx) * CC);

    if (lane < 3) __stcs(o + lane, p[lane]);

    const float4 v = __ldg(f + lane);   // 32 lanes x float4 = full 128-float row
    float* od = o + 3 + lane * 4;
    __stcs(od + 0, v.x);
    __stcs(od + 1, v.y);
    __stcs(od + 2, v.z);
    __stcs(od + 3, v.w);
}

extern "C" void kernel_launch(void* const* d_in, const int* in_sizes, int n_in,
                              void* d_out, int out_size) {
    const float* points = (const float*)d_in[0];   // (B, N, 3)
    const float* feats  = (const float*)d_in[1];   // (B, N, C)
    const float* boxes  = (const float*)d_in[2];   // (B, M, 7)
    float* out = (float*)d_out;

    float* flags = ((size_t)out_size >= POOLED_ELEMS + NBOX)
                 ? (out + POOLED_ELEMS) : nullptr;

    mask_kernel<<<1024, 256>>>(points, boxes);
    compact_kernel<<<NBOX, 512>>>(flags);

    const int total_warps = NBOX * SS;             // one warp per sample row
    phase2_kernel<<<total_warps / 8, 256>>>(points, feats, out);
}